// round 4
// baseline (speedup 1.0000x reference)
#include <cuda_runtime.h>
#include <math.h>
#include <stdint.h>

#define B_   32
#define G_   15
#define K_   2048
#define NG   480            // B_*G_
#define NPTS 983040         // NG*K_
#define TILE_P 128
#define ZSTR 68             // sZ row stride (uint32 tf32 values), conflict-free frag loads
#define OUT_LF_OFF 8192     // gf is 32*256 floats, local_features follows

__constant__ int c_split[15] = {0,1,8, 2,4,6, 3,5,7, 9,11,13, 10,12,14};

// ---------------- device scratch (no allocations allowed) ----------------
__device__ float  g_cent[NG*3];
__device__ float  g_S0p[NG*6];
__device__ float4 g_w0s[64];            // {s*w0, s*w1, s*w2, bias} fused layer-0 BN
__device__ float  g_max1[NG*64];
__device__ float  g_min1[NG*64];
__device__ float  g_psum1[NG*64];
__device__ float  g_psq1[NG*64];
__device__ float  g_sc1[64];
__device__ float  g_bi1[64];
__device__ float  g_lf1[NG*64];
__device__ float  g_feats2[480*67];
__device__ float  g_yA[480*128];
__device__ float  g_yB[480*128];
__device__ float  g_scaleA[128];
__device__ float  g_biasA[128];
__device__ float  g_scaleB[128];
__device__ float  g_biasB[128];
__device__ float  g_s3in[160*131];
__device__ float  g_yC[160*256];
__device__ float  g_yD[160*256];
__device__ float  g_scaleC[256];
__device__ float  g_biasC[256];
__device__ float  g_scaleD[256];
__device__ float  g_biasD[256];

__device__ __forceinline__ uint32_t f2tf(float f) {
    uint32_t u;
    asm("cvt.rna.tf32.f32 %0, %1;" : "=r"(u) : "f"(f));
    return u;
}

#define MMA_TF32(d, a, b)                                                     \
    asm volatile(                                                             \
        "mma.sync.aligned.m16n8k8.row.col.f32.tf32.tf32.f32 "                 \
        "{%0,%1,%2,%3}, {%4,%5,%6,%7}, {%8,%9}, {%0,%1,%2,%3};"               \
        : "+f"((d)[0]), "+f"((d)[1]), "+f"((d)[2]), "+f"((d)[3])              \
        : "r"((a)[0]), "r"((a)[1]), "r"((a)[2]), "r"((a)[3]),                 \
          "r"((b)[0]), "r"((b)[1]))

// ---------------- stage 1: centroids + 3x3 second-moment partials ----------------
__global__ void k_centroid(const float* __restrict__ x, float* __restrict__ out) {
    __shared__ float red[9*256];
    int blk = blockIdx.x, t = threadIdx.x;
    const float* xg = x + (size_t)blk * (K_*3);
    float s0=0,s1=0,s2=0,m00=0,m01=0,m02=0,m11=0,m12=0,m22=0;
    for (int p = t; p < K_; p += 256) {
        float a = xg[p*3+0], b = xg[p*3+1], c = xg[p*3+2];
        s0+=a; s1+=b; s2+=c;
        m00=fmaf(a,a,m00); m01=fmaf(a,b,m01); m02=fmaf(a,c,m02);
        m11=fmaf(b,b,m11); m12=fmaf(b,c,m12); m22=fmaf(c,c,m22);
    }
    red[0*256+t]=s0; red[1*256+t]=s1; red[2*256+t]=s2;
    red[3*256+t]=m00; red[4*256+t]=m01; red[5*256+t]=m02;
    red[6*256+t]=m11; red[7*256+t]=m12; red[8*256+t]=m22;
    __syncthreads();
    for (int s = 128; s > 0; s >>= 1) {
        if (t < s) {
            #pragma unroll
            for (int j = 0; j < 9; j++) red[j*256+t] += red[j*256+t+s];
        }
        __syncthreads();
    }
    if (t == 0) {
        const float invK = 1.0f / (float)K_;
        float C0 = red[0]*invK, C1 = red[256]*invK, C2 = red[512]*invK;
        g_cent[blk*3+0]=C0; g_cent[blk*3+1]=C1; g_cent[blk*3+2]=C2;
        g_S0p[blk*6+0] = red[3*256] - (float)K_*C0*C0;
        g_S0p[blk*6+1] = red[4*256] - (float)K_*C0*C1;
        g_S0p[blk*6+2] = red[5*256] - (float)K_*C0*C2;
        g_S0p[blk*6+3] = red[6*256] - (float)K_*C1*C1;
        g_S0p[blk*6+4] = red[7*256] - (float)K_*C1*C2;
        g_S0p[blk*6+5] = red[8*256] - (float)K_*C2*C2;
        int b = blk / G_, g = blk % G_;
        out[OUT_LF_OFF + (b*67+0)*15 + g] = C0;
        out[OUT_LF_OFF + (b*67+1)*15 + g] = C1;
        out[OUT_LF_OFF + (b*67+2)*15 + g] = C2;
    }
}

// layer-0 BN: mean is exactly 0; var = W0 S0 W0^T / N. Fuse scale into W0 rows.
__global__ void k_bn0(const float* __restrict__ W0, const float* __restrict__ g0,
                      const float* __restrict__ b0) {
    __shared__ float S[6];
    int t = threadIdx.x, w = t >> 5, lane = t & 31;
    if (w < 6) {
        float s = 0.f;
        for (int p = lane; p < NG; p += 32) s += g_S0p[p*6 + w];
        #pragma unroll
        for (int o = 16; o > 0; o >>= 1) s += __shfl_down_sync(0xffffffffu, s, o);
        if (lane == 0) S[w] = s;
    }
    __syncthreads();
    if (t < 64) {
        float w0 = W0[t*3+0], w1 = W0[t*3+1], w2 = W0[t*3+2];
        float var = (w0*w0*S[0] + w1*w1*S[3] + w2*w2*S[5]
                   + 2.f*(w0*w1*S[1] + w0*w2*S[2] + w1*w2*S[4])) * (1.0f/(float)NPTS);
        float scl = g0[t] * rsqrtf(var + 1e-5f);
        g_w0s[t] = make_float4(scl*w0, scl*w1, scl*w2, b0[t]);
    }
}

// ---------------- stage 1 main pass: 3xTF32 tensor-core GEMM + fused stats ----------------
// y1^T[128pt x 64ch] = z^T[128 x 64] @ W1^T  via mma.sync m16n8k8 tf32 with
// error compensation: z = zhi+zlo, W = Whi+Wlo; y ~= zhi*Whi + zhi*Wlo + zlo*Whi.
// 8 warps: 4 (m) x 2 (n); warp owns 32 pts x 32 ch. B-hi frags resident in regs.
__global__ void __launch_bounds__(256,1) k_main(const float* __restrict__ x,
                                                const float* __restrict__ W1) {
    extern __shared__ float smem[];
    uint32_t* sWhi = (uint32_t*)smem;                         // 4096
    uint32_t* sWlo = (uint32_t*)(smem + 4096);                // 4096
    uint32_t* sZhi = (uint32_t*)(smem + 8192);                // 128*ZSTR
    uint32_t* sZlo = (uint32_t*)(smem + 8192 + TILE_P*ZSTR);  // 128*ZSTR
    float*    sRed = smem + 8192 + 2*TILE_P*ZSTR;             // 64*32 = 2048
    float4*   sW0s = (float4*)(smem + 8192 + 2*TILE_P*ZSTR + 2048); // 64 float4
    float*    sCen = smem + 8192 + 2*TILE_P*ZSTR + 2048 + 256;      // 3

    const int blk = blockIdx.x, t = threadIdx.x;
    const int lane = t & 31, w = t >> 5;
    const int wm = w >> 1, wn = w & 1;
    const int gid = lane >> 2, tig = lane & 3;

    for (int j = t; j < 4096; j += 256) {
        float wv = W1[j];
        uint32_t hi = f2tf(wv);
        sWhi[j] = hi;
        sWlo[j] = f2tf(wv - __uint_as_float(hi));
    }
    if (t < 64) sW0s[t] = g_w0s[t];
    if (t < 3)  sCen[t] = g_cent[blk*3 + t];
    __syncthreads();

    // resident B-hi fragments: bh[nt][k0][2]
    uint32_t bh[4][8][2];
    {
        const int n0 = wn * 32;
        #pragma unroll
        for (int nt = 0; nt < 4; nt++)
            #pragma unroll
            for (int k0 = 0; k0 < 8; k0++) {
                const uint32_t* row = sWhi + (n0 + nt*8 + gid)*64 + k0*8 + tig;
                bh[nt][k0][0] = row[0];
                bh[nt][k0][1] = row[4];
            }
    }

    const float* xg = x + (size_t)blk * (K_*3);
    const float c0 = sCen[0], c1 = sCen[1], c2v = sCen[2];
    const int p1 = t >> 1, h = t & 1;      // phase-1 mapping: 2 threads/pt, 32 ch each
    const int wlo_base = wn*32*64;         // this warp's n-block in sWlo

    float mx[8], mn[8], sm[8], sq[8];
    #pragma unroll
    for (int s = 0; s < 8; s++) { mx[s]=-3.402823e38f; mn[s]=3.402823e38f; sm[s]=0.f; sq[s]=0.f; }

    for (int tb = 0; tb < K_; tb += TILE_P) {
        // phase 1: z (BN0-fused relu) -> hi/lo tf32 split
        {
            const float* xp = xg + (size_t)(tb + p1)*3;
            float r0 = xp[0]-c0, r1 = xp[1]-c1, r2 = xp[2]-c2v;
            uint32_t* zh = sZhi + p1*ZSTR + h*32;
            uint32_t* zl = sZlo + p1*ZSTR + h*32;
            #pragma unroll
            for (int cj = 0; cj < 32; cj++) {
                float4 q = sW0s[h*32 + cj];
                float z = fmaxf(fmaf(q.x, r0, fmaf(q.y, r1, fmaf(q.z, r2, q.w))), 0.f);
                uint32_t hi = f2tf(z);
                zh[cj] = hi;
                zl[cj] = f2tf(z - __uint_as_float(hi));
            }
        }
        __syncthreads();

        // phase 2: 3xTF32 tensor-core GEMM
        float acc[2][4][4];
        #pragma unroll
        for (int m = 0; m < 2; m++)
            #pragma unroll
            for (int nt = 0; nt < 4; nt++)
                #pragma unroll
                for (int r = 0; r < 4; r++) acc[m][nt][r] = 0.f;

        const int ptb = wm * 32;
        #pragma unroll
        for (int k0 = 0; k0 < 8; k0++) {
            uint32_t ah[2][4], al[2][4];
            #pragma unroll
            for (int m = 0; m < 2; m++) {
                const int off = (ptb + m*16 + gid)*ZSTR + k0*8 + tig;
                const uint32_t* zh = sZhi + off;
                const uint32_t* zl = sZlo + off;
                ah[m][0] = zh[0];          al[m][0] = zl[0];
                ah[m][1] = zh[8*ZSTR];     al[m][1] = zl[8*ZSTR];
                ah[m][2] = zh[4];          al[m][2] = zl[4];
                ah[m][3] = zh[8*ZSTR+4];   al[m][3] = zl[8*ZSTR+4];
            }
            uint32_t bl[4][2];
            #pragma unroll
            for (int nt = 0; nt < 4; nt++) {
                const uint32_t* row = sWlo + wlo_base + (nt*8 + gid)*64 + k0*8 + tig;
                bl[nt][0] = row[0];
                bl[nt][1] = row[4];
            }
            #pragma unroll
            for (int m = 0; m < 2; m++)
                #pragma unroll
                for (int nt = 0; nt < 4; nt++) {
                    MMA_TF32(acc[m][nt], ah[m], bh[nt][k0]);
                    MMA_TF32(acc[m][nt], ah[m], bl[nt]);
                    MMA_TF32(acc[m][nt], al[m], bh[nt][k0]);
                }
        }

        // fold stats in-register
        #pragma unroll
        for (int m = 0; m < 2; m++)
            #pragma unroll
            for (int nt = 0; nt < 4; nt++)
                #pragma unroll
                for (int r = 0; r < 4; r++) {
                    float v = acc[m][nt][r];
                    int s = nt*2 + (r & 1);
                    mx[s] = fmaxf(mx[s], v);
                    mn[s] = fminf(mn[s], v);
                    sm[s] += v;
                    sq[s] = fmaf(v, v, sq[s]);
                }
        __syncthreads();   // protect sZ before next tile's phase 1
    }

    // deterministic cross-thread reductions: 32 partials per channel
    // ch(s) = wn*32 + (s>>1)*8 + 2*tig + (s&1); slot = wm*8 + gid
    const int slot = wm*8 + gid;
    #pragma unroll
    for (int s = 0; s < 8; s++) sRed[(wn*32 + (s>>1)*8 + 2*tig + (s&1))*32 + slot] = mx[s];
    __syncthreads();
    if (t < 64) {
        float v = sRed[t*32];
        #pragma unroll
        for (int j = 1; j < 32; j++) v = fmaxf(v, sRed[t*32+j]);
        g_max1[blk*64+t] = v;
    }
    __syncthreads();
    #pragma unroll
    for (int s = 0; s < 8; s++) sRed[(wn*32 + (s>>1)*8 + 2*tig + (s&1))*32 + slot] = mn[s];
    __syncthreads();
    if (t < 64) {
        float v = sRed[t*32];
        #pragma unroll
        for (int j = 1; j < 32; j++) v = fminf(v, sRed[t*32+j]);
        g_min1[blk*64+t] = v;
    }
    __syncthreads();
    #pragma unroll
    for (int s = 0; s < 8; s++) sRed[(wn*32 + (s>>1)*8 + 2*tig + (s&1))*32 + slot] = sm[s];
    __syncthreads();
    if (t < 64) {
        float v = 0.f;
        #pragma unroll
        for (int j = 0; j < 32; j++) v += sRed[t*32+j];
        g_psum1[blk*64+t] = v;
    }
    __syncthreads();
    #pragma unroll
    for (int s = 0; s < 8; s++) sRed[(wn*32 + (s>>1)*8 + 2*tig + (s&1))*32 + slot] = sq[s];
    __syncthreads();
    if (t < 64) {
        float v = 0.f;
        #pragma unroll
        for (int j = 0; j < 32; j++) v += sRed[t*32+j];
        g_psq1[blk*64+t] = v;
    }
}

// layer-1 BN stats: one block per channel, tree-reduce 480 groups
__global__ void k_bn1_stats(const float* __restrict__ g1, const float* __restrict__ b1) {
    __shared__ float rs[256], rq[256];
    int c = blockIdx.x, t = threadIdx.x;
    float s = 0.f, q = 0.f;
    for (int p = t; p < NG; p += 256) { s += g_psum1[p*64+c]; q += g_psq1[p*64+c]; }
    rs[t] = s; rq[t] = q;
    __syncthreads();
    for (int o = 128; o > 0; o >>= 1) {
        if (t < o) { rs[t] += rs[t+o]; rq[t] += rq[t+o]; }
        __syncthreads();
    }
    if (t == 0) {
        float mean = rs[0] * (1.0f/(float)NPTS);
        float var  = rq[0] * (1.0f/(float)NPTS) - mean*mean;
        float scl  = g1[c] * rsqrtf(var + 1e-5f);
        g_sc1[c] = scl;
        g_bi1[c] = b1[c] - mean*scl;
    }
}

// lf1 via monotone max/min trick + local_features output (fully parallel)
__global__ void k_lf1(float* __restrict__ out) {
    int idx = blockIdx.x * 256 + threadIdx.x;   // 120 blocks x 256 = 30720
    if (idx >= NG*64) return;
    int c = idx & 63, grp = idx >> 6;
    float scl = g_sc1[c];
    float v  = (scl >= 0.f) ? g_max1[idx] : g_min1[idx];
    float lf = fmaxf(fmaf(scl, v, g_bi1[c]), 0.f);
    g_lf1[idx] = lf;
    int b = grp / G_, g = grp % G_;
    out[OUT_LF_OFF + (b*67 + 3 + c)*15 + g] = lf;
}

// ---------------- stage 2 input assembly (+ stage-3 rel3 channels) ----------------
__global__ void k_feats2() {
    __shared__ float sc2[160*3];
    int t = threadIdx.x; // 160 threads: t = b*5+s
    int b = t / 5, s = t % 5;
    float c2[3];
    int ga = c_split[s*3+0], gb = c_split[s*3+1], gc = c_split[s*3+2];
    #pragma unroll
    for (int i = 0; i < 3; i++) {
        c2[i] = (g_cent[(b*15+ga)*3+i] + g_cent[(b*15+gb)*3+i] + g_cent[(b*15+gc)*3+i]) * (1.f/3.f);
        sc2[t*3+i] = c2[i];
    }
    #pragma unroll
    for (int m = 0; m < 3; m++) {
        int g = c_split[s*3+m];
        int base = ((b*5+s)*3 + m) * 67;
        #pragma unroll
        for (int i = 0; i < 3; i++) g_feats2[base+i] = g_cent[(b*15+g)*3+i] - c2[i];
        for (int c = 0; c < 64; c++) g_feats2[base+3+c] = g_lf1[(b*15+g)*64+c];
    }
    __syncthreads();
    #pragma unroll
    for (int i = 0; i < 3; i++) {
        float c3 = 0.f;
        #pragma unroll
        for (int ss = 0; ss < 5; ss++) c3 += sc2[(b*5+ss)*3+i];
        c3 *= 0.2f;
        g_s3in[(b*5+s)*131 + i] = c2[i] - c3;
    }
}

// ---------------- stage 2/3 small GEMMs + BN stats ----------------
__global__ void k_gemmA(const float* __restrict__ W) { // (128,67) @ feats2
    int p = blockIdx.x, c = threadIdx.x; // 480 x 128
    __shared__ float f[67];
    if (c < 67) f[c] = g_feats2[p*67+c];
    __syncthreads();
    float acc = 0.f;
    const float* w = W + c*67;
    #pragma unroll
    for (int i = 0; i < 67; i++) acc = fmaf(w[i], f[i], acc);
    g_yA[p*128+c] = acc;
}

__global__ void k_statsA(const float* __restrict__ g, const float* __restrict__ b) {
    __shared__ float rs[256], rq[256];
    int c = blockIdx.x, t = threadIdx.x; // 128 blocks x 256
    float s = 0.f, q = 0.f;
    for (int p = t; p < 480; p += 256) { float v = g_yA[p*128+c]; s += v; q = fmaf(v,v,q); }
    rs[t] = s; rq[t] = q;
    __syncthreads();
    for (int o = 128; o > 0; o >>= 1) {
        if (t < o) { rs[t] += rs[t+o]; rq[t] += rq[t+o]; }
        __syncthreads();
    }
    if (t == 0) {
        float mean = rs[0] * (1.f/480.f);
        float var  = rq[0] * (1.f/480.f) - mean*mean;
        float scl  = g[c] * rsqrtf(var + 1e-5f);
        g_scaleA[c] = scl;
        g_biasA[c]  = b[c] - mean*scl;
    }
}

__global__ void k_gemmB(const float* __restrict__ W) { // (128,128)
    int p = blockIdx.x, c = threadIdx.x;
    __shared__ float z[128];
    z[c] = fmaxf(fmaf(g_scaleA[c], g_yA[p*128+c], g_biasA[c]), 0.f);
    __syncthreads();
    float acc = 0.f;
    const float* w = W + c*128;
    #pragma unroll
    for (int i = 0; i < 128; i++) acc = fmaf(w[i], z[i], acc);
    g_yB[p*128+c] = acc;
}

__global__ void k_statsB(const float* __restrict__ g, const float* __restrict__ b) {
    __shared__ float rs[256], rq[256];
    int c = blockIdx.x, t = threadIdx.x; // 128 blocks x 256
    float s = 0.f, q = 0.f;
    for (int p = t; p < 480; p += 256) { float v = g_yB[p*128+c]; s += v; q = fmaf(v,v,q); }
    rs[t] = s; rq[t] = q;
    __syncthreads();
    for (int o = 128; o > 0; o >>= 1) {
        if (t < o) { rs[t] += rs[t+o]; rq[t] += rq[t+o]; }
        __syncthreads();
    }
    if (t == 0) {
        float mean = rs[0] * (1.f/480.f);
        float var  = rq[0] * (1.f/480.f) - mean*mean;
        float scl  = g[c] * rsqrtf(var + 1e-5f);
        g_scaleB[c] = scl;
        g_biasB[c]  = b[c] - mean*scl;
    }
}

// s3in assembly: max-over-3 with BN monotone trick (160 blocks x 128 threads)
__global__ void k_s3in() {
    int bs = blockIdx.x, c = threadIdx.x;
    float scl = g_scaleB[c], bi = g_biasB[c];
    float v0 = g_yB[(bs*3+0)*128+c];
    float v1 = g_yB[(bs*3+1)*128+c];
    float v2 = g_yB[(bs*3+2)*128+c];
    float v  = (scl >= 0.f) ? fmaxf(v0, fmaxf(v1, v2)) : fminf(v0, fminf(v1, v2));
    g_s3in[bs*131 + 3 + c] = fmaxf(fmaf(scl, v, bi), 0.f);
}

__global__ void k_gemmC(const float* __restrict__ W) { // (256,131)
    int bs = blockIdx.x, c = threadIdx.x; // 160 x 256
    __shared__ float f[131];
    if (c < 131) f[c] = g_s3in[bs*131+c];
    __syncthreads();
    float acc = 0.f;
    const float* w = W + c*131;
    #pragma unroll
    for (int i = 0; i < 131; i++) acc = fmaf(w[i], f[i], acc);
    g_yC[bs*256+c] = acc;
}

__global__ void k_statsC(const float* __restrict__ g, const float* __restrict__ b) {
    __shared__ float rs[256], rq[256];
    int c = blockIdx.x, t = threadIdx.x; // 256 blocks x 256
    float s = 0.f, q = 0.f;
    if (t < 160) { float v = g_yC[t*256+c]; s = v; q = v*v; }
    rs[t] = s; rq[t] = q;
    __syncthreads();
    for (int o = 128; o > 0; o >>= 1) {
        if (t < o) { rs[t] += rs[t+o]; rq[t] += rq[t+o]; }
        __syncthreads();
    }
    if (t == 0) {
        float mean = rs[0] * (1.f/160.f);
        float var  = rq[0] * (1.f/160.f) - mean*mean;
        float scl  = g[c] * rsqrtf(var + 1e-5f);
        g_scaleC[c] = scl;
        g_biasC[c]  = b[c] - mean*scl;
    }
}

__global__ void k_gemmD(const float* __restrict__ W) { // (256,256)
    int bs = blockIdx.x, c = threadIdx.x;
    __shared__ float z[256];
    z[c] = fmaxf(fmaf(g_scaleC[c], g_yC[bs*256+c], g_biasC[c]), 0.f);
    __syncthreads();
    float acc = 0.f;
    const float* w = W + c*256;
    #pragma unroll
    for (int i = 0; i < 256; i++) acc = fmaf(w[i], z[i], acc);
    g_yD[bs*256+c] = acc;
}

__global__ void k_statsD(const float* __restrict__ g, const float* __restrict__ b) {
    __shared__ float rs[256], rq[256];
    int c = blockIdx.x, t = threadIdx.x; // 256 blocks x 256
    float s = 0.f, q = 0.f;
    if (t < 160) { float v = g_yD[t*256+c]; s = v; q = v*v; }
    rs[t] = s; rq[t] = q;
    __syncthreads();
    for (int o = 128; o > 0; o >>= 1) {
        if (t < o) { rs[t] += rs[t+o]; rq[t] += rq[t+o]; }
        __syncthreads();
    }
    if (t == 0) {
        float mean = rs[0] * (1.f/160.f);
        float var  = rq[0] * (1.f/160.f) - mean*mean;
        float scl  = g[c] * rsqrtf(var + 1e-5f);
        g_scaleD[c] = scl;
        g_biasD[c]  = b[c] - mean*scl;
    }
}

// final output: max over 5 splits with BN monotone trick (32 blocks x 256 threads)
__global__ void k_out(float* __restrict__ out) {
    int bb = blockIdx.x, c = threadIdx.x;
    float scl = g_scaleD[c], bi = g_biasD[c];
    float v = (scl >= 0.f) ? -3.402823e38f : 3.402823e38f;
    #pragma unroll
    for (int ss = 0; ss < 5; ss++) {
        float y = g_yD[(bb*5+ss)*256+c];
        v = (scl >= 0.f) ? fmaxf(v, y) : fminf(v, y);
    }
    out[bb*256+c] = fmaxf(fmaf(scl, v, bi), 0.f);
}

// ---------------- launch ----------------
extern "C" void kernel_launch(void* const* d_in, const int* in_sizes, int n_in,
                              void* d_out, int out_size) {
    const float* x      = (const float*)d_in[0];
    const float* la0_w0 = (const float*)d_in[1];
    const float* la0_g0 = (const float*)d_in[2];
    const float* la0_b0 = (const float*)d_in[3];
    const float* la0_w1 = (const float*)d_in[4];
    const float* la0_g1 = (const float*)d_in[5];
    const float* la0_b1 = (const float*)d_in[6];
    const float* la1_w0 = (const float*)d_in[7];
    const float* la1_g0 = (const float*)d_in[8];
    const float* la1_b0 = (const float*)d_in[9];
    const float* la1_w1 = (const float*)d_in[10];
    const float* la1_g1 = (const float*)d_in[11];
    const float* la1_b1 = (const float*)d_in[12];
    const float* la2_w0 = (const float*)d_in[13];
    const float* la2_g0 = (const float*)d_in[14];
    const float* la2_b0 = (const float*)d_in[15];
    const float* la2_w1 = (const float*)d_in[16];
    const float* la2_g1 = (const float*)d_in[17];
    const float* la2_b1 = (const float*)d_in[18];
    float* out = (float*)d_out;

    const int SMEM_MAIN = (8192 + 2*TILE_P*ZSTR + 2048 + 256 + 8) * (int)sizeof(float);
    cudaFuncSetAttribute(k_main, cudaFuncAttributeMaxDynamicSharedMemorySize, SMEM_MAIN);

    k_centroid<<<NG, 256>>>(x, out);
    k_bn0<<<1, 192>>>(la0_w0, la0_g0, la0_b0);
    k_main<<<NG, 256, SMEM_MAIN>>>(x, la0_w1);
    k_bn1_stats<<<64, 256>>>(la0_g1, la0_b1);
    k_lf1<<<120, 256>>>(out);
    k_feats2<<<1, 160>>>();
    k_gemmA<<<480, 128>>>(la1_w0);
    k_statsA<<<128, 256>>>(la1_g0, la1_b0);
    k_gemmB<<<480, 128>>>(la1_w1);
    k_statsB<<<128, 256>>>(la1_g1, la1_b1);
    k_s3in<<<160, 128>>>();
    k_gemmC<<<160, 256>>>(la2_w0);
    k_statsC<<<256, 256>>>(la2_g0, la2_b0);
    k_gemmD<<<160, 256>>>(la2_w1);
    k_statsD<<<256, 256>>>(la2_g1, la2_b1);
    k_out<<<32, 256>>>(out);
}

// round 5
// speedup vs baseline: 1.6861x; 1.6861x over previous
#include <cuda_runtime.h>
#include <cuda_fp16.h>
#include <math.h>
#include <stdint.h>

#define B_   32
#define G_   15
#define K_   2048
#define NG   480            // B_*G_
#define NPTS 983040         // NG*K_
#define TILE_P 128
#define ZSTR 36             // sZ row stride (uint32 = 2 fp16), conflict-free frag loads
#define OUT_LF_OFF 8192     // gf is 32*256 floats, local_features follows

__constant__ int c_split[15] = {0,1,8, 2,4,6, 3,5,7, 9,11,13, 10,12,14};

// ---------------- device scratch (no allocations allowed) ----------------
__device__ float  g_cent[NG*3];
__device__ float  g_S0p[NG*6];
__device__ float4 g_w0s[64];            // {s*w0, s*w1, s*w2, bias} fused layer-0 BN
__device__ float  g_max1[NG*64];
__device__ float  g_min1[NG*64];
__device__ float  g_psum1[NG*64];
__device__ float  g_psq1[NG*64];
__device__ float  g_sc1[64];
__device__ float  g_bi1[64];
__device__ float  g_lf1[NG*64];
__device__ float  g_feats2[480*67];
__device__ float  g_yA[480*128];
__device__ float  g_yB[480*128];
__device__ float  g_scaleA[128];
__device__ float  g_biasA[128];
__device__ float  g_scaleB[128];
__device__ float  g_biasB[128];
__device__ float  g_s3in[160*131];
__device__ float  g_yC[160*256];
__device__ float  g_yD[160*256];
__device__ float  g_scaleC[256];
__device__ float  g_biasC[256];
__device__ float  g_scaleD[256];
__device__ float  g_biasD[256];

__device__ __forceinline__ uint32_t h2u(__half2 h) {
    uint32_t u;
    memcpy(&u, &h, 4);
    return u;
}

#define MMA_F16(d, a, b)                                                      \
    asm volatile(                                                             \
        "mma.sync.aligned.m16n8k16.row.col.f32.f16.f16.f32 "                  \
        "{%0,%1,%2,%3}, {%4,%5,%6,%7}, {%8,%9}, {%0,%1,%2,%3};"               \
        : "+f"((d)[0]), "+f"((d)[1]), "+f"((d)[2]), "+f"((d)[3])              \
        : "r"((a)[0]), "r"((a)[1]), "r"((a)[2]), "r"((a)[3]),                 \
          "r"((b)[0]), "r"((b)[1]))

// ---------------- stage 1: centroids + 3x3 second-moment partials ----------------
__global__ void k_centroid(const float* __restrict__ x, float* __restrict__ out) {
    __shared__ float red[9*256];
    int blk = blockIdx.x, t = threadIdx.x;
    const float* xg = x + (size_t)blk * (K_*3);
    float s0=0,s1=0,s2=0,m00=0,m01=0,m02=0,m11=0,m12=0,m22=0;
    for (int p = t; p < K_; p += 256) {
        float a = xg[p*3+0], b = xg[p*3+1], c = xg[p*3+2];
        s0+=a; s1+=b; s2+=c;
        m00=fmaf(a,a,m00); m01=fmaf(a,b,m01); m02=fmaf(a,c,m02);
        m11=fmaf(b,b,m11); m12=fmaf(b,c,m12); m22=fmaf(c,c,m22);
    }
    red[0*256+t]=s0; red[1*256+t]=s1; red[2*256+t]=s2;
    red[3*256+t]=m00; red[4*256+t]=m01; red[5*256+t]=m02;
    red[6*256+t]=m11; red[7*256+t]=m12; red[8*256+t]=m22;
    __syncthreads();
    for (int s = 128; s > 0; s >>= 1) {
        if (t < s) {
            #pragma unroll
            for (int j = 0; j < 9; j++) red[j*256+t] += red[j*256+t+s];
        }
        __syncthreads();
    }
    if (t == 0) {
        const float invK = 1.0f / (float)K_;
        float C0 = red[0]*invK, C1 = red[256]*invK, C2 = red[512]*invK;
        g_cent[blk*3+0]=C0; g_cent[blk*3+1]=C1; g_cent[blk*3+2]=C2;
        g_S0p[blk*6+0] = red[3*256] - (float)K_*C0*C0;
        g_S0p[blk*6+1] = red[4*256] - (float)K_*C0*C1;
        g_S0p[blk*6+2] = red[5*256] - (float)K_*C0*C2;
        g_S0p[blk*6+3] = red[6*256] - (float)K_*C1*C1;
        g_S0p[blk*6+4] = red[7*256] - (float)K_*C1*C2;
        g_S0p[blk*6+5] = red[8*256] - (float)K_*C2*C2;
        int b = blk / G_, g = blk % G_;
        out[OUT_LF_OFF + (b*67+0)*15 + g] = C0;
        out[OUT_LF_OFF + (b*67+1)*15 + g] = C1;
        out[OUT_LF_OFF + (b*67+2)*15 + g] = C2;
    }
}

// layer-0 BN: mean is exactly 0; var = W0 S0 W0^T / N. Fuse scale into W0 rows.
__global__ void k_bn0(const float* __restrict__ W0, const float* __restrict__ g0,
                      const float* __restrict__ b0) {
    __shared__ float S[6];
    int t = threadIdx.x, w = t >> 5, lane = t & 31;
    if (w < 6) {
        float s = 0.f;
        for (int p = lane; p < NG; p += 32) s += g_S0p[p*6 + w];
        #pragma unroll
        for (int o = 16; o > 0; o >>= 1) s += __shfl_down_sync(0xffffffffu, s, o);
        if (lane == 0) S[w] = s;
    }
    __syncthreads();
    if (t < 64) {
        float w0 = W0[t*3+0], w1 = W0[t*3+1], w2 = W0[t*3+2];
        float var = (w0*w0*S[0] + w1*w1*S[3] + w2*w2*S[5]
                   + 2.f*(w0*w1*S[1] + w0*w2*S[2] + w1*w2*S[4])) * (1.0f/(float)NPTS);
        float scl = g0[t] * rsqrtf(var + 1e-5f);
        g_w0s[t] = make_float4(scl*w0, scl*w1, scl*w2, b0[t]);
    }
}

// ---------------- stage 1 main pass: fp16 3-term compensated HMMA + fused stats ----------------
// y1^T[128pt x 64ch] = z^T @ W1^T via mma.sync m16n8k16 fp16:
// z = zh+zl, W = Wh+Wl; y ~= zh*Wh + zh*Wl + zl*Wh (drop zl*Wl ~2^-22).
// 8 warps: 4(m) x 2(n); warp owns 32 pts x 32 ch. Both B-hi and B-lo frags in regs.
__global__ void __launch_bounds__(256,1) k_main(const float* __restrict__ x,
                                                const float* __restrict__ W1) {
    extern __shared__ float smem[];
    uint32_t* sWhi = (uint32_t*)smem;                         // 64*32 uint32
    uint32_t* sWlo = sWhi + 2048;                             // 64*32
    uint32_t* sZhi = sWlo + 2048;                             // 128*ZSTR
    uint32_t* sZlo = sZhi + TILE_P*ZSTR;                      // 128*ZSTR
    float*    sRed = (float*)(sZlo + TILE_P*ZSTR);            // 64*32 = 2048
    float4*   sW0s = (float4*)(sRed + 2048);                  // 64 float4
    float*    sCen = (float*)(sW0s + 64);                     // 3

    const int blk = blockIdx.x, t = threadIdx.x;
    const int lane = t & 31, w = t >> 5;
    const int wm = w >> 1, wn = w & 1;
    const int gid = lane >> 2, tig = lane & 3;

    // pack W1 into fp16 hi/lo, layout [n][k/2] uint32
    for (int idx = t; idx < 2048; idx += 256) {
        int n = idx >> 5, kk = idx & 31;
        float w0 = W1[n*64 + 2*kk], w1 = W1[n*64 + 2*kk + 1];
        __half2 hi2 = __floats2half2_rn(w0, w1);
        float2 bk = __half22float2(hi2);
        __half2 lo2 = __floats2half2_rn(w0 - bk.x, w1 - bk.y);
        sWhi[idx] = h2u(hi2);
        sWlo[idx] = h2u(lo2);
    }
    if (t < 64) sW0s[t] = g_w0s[t];
    if (t < 3)  sCen[t] = g_cent[blk*3 + t];
    __syncthreads();

    // resident B fragments (hi and lo): [nt][k0][2]
    uint32_t bh[4][4][2], bl[4][4][2];
    {
        const int n0 = wn * 32;
        #pragma unroll
        for (int nt = 0; nt < 4; nt++)
            #pragma unroll
            for (int k0 = 0; k0 < 4; k0++) {
                const int base = (n0 + nt*8 + gid)*32 + k0*8 + tig;
                bh[nt][k0][0] = sWhi[base];
                bh[nt][k0][1] = sWhi[base + 4];
                bl[nt][k0][0] = sWlo[base];
                bl[nt][k0][1] = sWlo[base + 4];
            }
    }

    const float* xg = x + (size_t)blk * (K_*3);
    const float c0 = sCen[0], c1 = sCen[1], c2v = sCen[2];
    // phase-1 mapping: h = channel half (warps 0-3 -> ch 0..31, 4-7 -> 32..63),
    // p1 = point 0..127 (one per lane within the 4-warp set)
    const int h  = w >> 2;
    const int p1 = (w & 3) * 32 + lane;

    float mx[8], mn[8], sm[8], sq[8];
    #pragma unroll
    for (int s = 0; s < 8; s++) { mx[s]=-3.402823e38f; mn[s]=3.402823e38f; sm[s]=0.f; sq[s]=0.f; }

    for (int tb = 0; tb < K_; tb += TILE_P) {
        // phase 1: z (BN0-fused relu) -> fp16 hi/lo split, packed 2 ch per uint32
        {
            const float* xp = xg + (size_t)(tb + p1)*3;
            float r0 = xp[0]-c0, r1 = xp[1]-c1, r2 = xp[2]-c2v;
            uint32_t zh2[16], zl2[16];
            #pragma unroll
            for (int j = 0; j < 16; j++) {
                float4 qa = sW0s[h*32 + 2*j];
                float4 qb = sW0s[h*32 + 2*j + 1];
                float za = fmaxf(fmaf(qa.x, r0, fmaf(qa.y, r1, fmaf(qa.z, r2, qa.w))), 0.f);
                float zb = fmaxf(fmaf(qb.x, r0, fmaf(qb.y, r1, fmaf(qb.z, r2, qb.w))), 0.f);
                __half2 hi2 = __floats2half2_rn(za, zb);
                float2 bk = __half22float2(hi2);
                __half2 lo2 = __floats2half2_rn(za - bk.x, zb - bk.y);
                zh2[j] = h2u(hi2);
                zl2[j] = h2u(lo2);
            }
            uint4* zh = (uint4*)(sZhi + p1*ZSTR + h*16);
            uint4* zl = (uint4*)(sZlo + p1*ZSTR + h*16);
            #pragma unroll
            for (int j4 = 0; j4 < 4; j4++) {
                zh[j4] = make_uint4(zh2[j4*4], zh2[j4*4+1], zh2[j4*4+2], zh2[j4*4+3]);
                zl[j4] = make_uint4(zl2[j4*4], zl2[j4*4+1], zl2[j4*4+2], zl2[j4*4+3]);
            }
        }
        __syncthreads();

        // phase 2: 3-term fp16 tensor-core GEMM
        float acc[2][4][4];
        #pragma unroll
        for (int m = 0; m < 2; m++)
            #pragma unroll
            for (int nt = 0; nt < 4; nt++)
                #pragma unroll
                for (int r = 0; r < 4; r++) acc[m][nt][r] = 0.f;

        const int ptb = wm * 32;
        #pragma unroll
        for (int k0 = 0; k0 < 4; k0++) {
            uint32_t ah[2][4], al[2][4];
            #pragma unroll
            for (int m = 0; m < 2; m++) {
                const int off = (ptb + m*16 + gid)*ZSTR + k0*8 + tig;
                ah[m][0] = sZhi[off];            al[m][0] = sZlo[off];
                ah[m][1] = sZhi[off + 8*ZSTR];   al[m][1] = sZlo[off + 8*ZSTR];
                ah[m][2] = sZhi[off + 4];        al[m][2] = sZlo[off + 4];
                ah[m][3] = sZhi[off + 8*ZSTR+4]; al[m][3] = sZlo[off + 8*ZSTR+4];
            }
            #pragma unroll
            for (int m = 0; m < 2; m++)
                #pragma unroll
                for (int nt = 0; nt < 4; nt++) {
                    MMA_F16(acc[m][nt], ah[m], bh[nt][k0]);
                    MMA_F16(acc[m][nt], ah[m], bl[nt][k0]);
                    MMA_F16(acc[m][nt], al[m], bh[nt][k0]);
                }
        }

        // fold stats in-register
        #pragma unroll
        for (int m = 0; m < 2; m++)
            #pragma unroll
            for (int nt = 0; nt < 4; nt++)
                #pragma unroll
                for (int r = 0; r < 4; r++) {
                    float v = acc[m][nt][r];
                    int s = nt*2 + (r & 1);
                    mx[s] = fmaxf(mx[s], v);
                    mn[s] = fminf(mn[s], v);
                    sm[s] += v;
                    sq[s] = fmaf(v, v, sq[s]);
                }
        __syncthreads();   // protect sZ before next tile's phase 1
    }

    // deterministic cross-thread reductions: 32 partials per channel
    // ch(s) = wn*32 + (s>>1)*8 + 2*tig + (s&1); slot = wm*8 + gid
    const int slot = wm*8 + gid;
    #pragma unroll
    for (int s = 0; s < 8; s++) sRed[(wn*32 + (s>>1)*8 + 2*tig + (s&1))*32 + slot] = mx[s];
    __syncthreads();
    if (t < 64) {
        float v = sRed[t*32];
        #pragma unroll
        for (int j = 1; j < 32; j++) v = fmaxf(v, sRed[t*32+j]);
        g_max1[blk*64+t] = v;
    }
    __syncthreads();
    #pragma unroll
    for (int s = 0; s < 8; s++) sRed[(wn*32 + (s>>1)*8 + 2*tig + (s&1))*32 + slot] = mn[s];
    __syncthreads();
    if (t < 64) {
        float v = sRed[t*32];
        #pragma unroll
        for (int j = 1; j < 32; j++) v = fminf(v, sRed[t*32+j]);
        g_min1[blk*64+t] = v;
    }
    __syncthreads();
    #pragma unroll
    for (int s = 0; s < 8; s++) sRed[(wn*32 + (s>>1)*8 + 2*tig + (s&1))*32 + slot] = sm[s];
    __syncthreads();
    if (t < 64) {
        float v = 0.f;
        #pragma unroll
        for (int j = 0; j < 32; j++) v += sRed[t*32+j];
        g_psum1[blk*64+t] = v;
    }
    __syncthreads();
    #pragma unroll
    for (int s = 0; s < 8; s++) sRed[(wn*32 + (s>>1)*8 + 2*tig + (s&1))*32 + slot] = sq[s];
    __syncthreads();
    if (t < 64) {
        float v = 0.f;
        #pragma unroll
        for (int j = 0; j < 32; j++) v += sRed[t*32+j];
        g_psq1[blk*64+t] = v;
    }
}

// layer-1 BN stats: one block per channel, tree-reduce 480 groups
__global__ void k_bn1_stats(const float* __restrict__ g1, const float* __restrict__ b1) {
    __shared__ float rs[256], rq[256];
    int c = blockIdx.x, t = threadIdx.x;
    float s = 0.f, q = 0.f;
    for (int p = t; p < NG; p += 256) { s += g_psum1[p*64+c]; q += g_psq1[p*64+c]; }
    rs[t] = s; rq[t] = q;
    __syncthreads();
    for (int o = 128; o > 0; o >>= 1) {
        if (t < o) { rs[t] += rs[t+o]; rq[t] += rq[t+o]; }
        __syncthreads();
    }
    if (t == 0) {
        float mean = rs[0] * (1.0f/(float)NPTS);
        float var  = rq[0] * (1.0f/(float)NPTS) - mean*mean;
        float scl  = g1[c] * rsqrtf(var + 1e-5f);
        g_sc1[c] = scl;
        g_bi1[c] = b1[c] - mean*scl;
    }
}

// lf1 via monotone max/min trick + local_features output (fully parallel)
__global__ void k_lf1(float* __restrict__ out) {
    int idx = blockIdx.x * 256 + threadIdx.x;   // 120 blocks x 256 = 30720
    if (idx >= NG*64) return;
    int c = idx & 63, grp = idx >> 6;
    float scl = g_sc1[c];
    float v  = (scl >= 0.f) ? g_max1[idx] : g_min1[idx];
    float lf = fmaxf(fmaf(scl, v, g_bi1[c]), 0.f);
    g_lf1[idx] = lf;
    int b = grp / G_, g = grp % G_;
    out[OUT_LF_OFF + (b*67 + 3 + c)*15 + g] = lf;
}

// ---------------- stage 2 input assembly (+ stage-3 rel3 channels) ----------------
__global__ void k_feats2() {
    __shared__ float sc2[160*3];
    int t = threadIdx.x; // 160 threads: t = b*5+s
    int b = t / 5, s = t % 5;
    float c2[3];
    int ga = c_split[s*3+0], gb = c_split[s*3+1], gc = c_split[s*3+2];
    #pragma unroll
    for (int i = 0; i < 3; i++) {
        c2[i] = (g_cent[(b*15+ga)*3+i] + g_cent[(b*15+gb)*3+i] + g_cent[(b*15+gc)*3+i]) * (1.f/3.f);
        sc2[t*3+i] = c2[i];
    }
    #pragma unroll
    for (int m = 0; m < 3; m++) {
        int g = c_split[s*3+m];
        int base = ((b*5+s)*3 + m) * 67;
        #pragma unroll
        for (int i = 0; i < 3; i++) g_feats2[base+i] = g_cent[(b*15+g)*3+i] - c2[i];
        for (int c = 0; c < 64; c++) g_feats2[base+3+c] = g_lf1[(b*15+g)*64+c];
    }
    __syncthreads();
    #pragma unroll
    for (int i = 0; i < 3; i++) {
        float c3 = 0.f;
        #pragma unroll
        for (int ss = 0; ss < 5; ss++) c3 += sc2[(b*5+ss)*3+i];
        c3 *= 0.2f;
        g_s3in[(b*5+s)*131 + i] = c2[i] - c3;
    }
}

// ---------------- stage 2/3 small GEMMs + BN stats ----------------
__global__ void k_gemmA(const float* __restrict__ W) { // (128,67) @ feats2
    int p = blockIdx.x, c = threadIdx.x; // 480 x 128
    __shared__ float f[67];
    if (c < 67) f[c] = g_feats2[p*67+c];
    __syncthreads();
    float acc = 0.f;
    const float* w = W + c*67;
    #pragma unroll
    for (int i = 0; i < 67; i++) acc = fmaf(w[i], f[i], acc);
    g_yA[p*128+c] = acc;
}

__global__ void k_statsA(const float* __restrict__ g, const float* __restrict__ b) {
    __shared__ float rs[256], rq[256];
    int c = blockIdx.x, t = threadIdx.x; // 128 blocks x 256
    float s = 0.f, q = 0.f;
    for (int p = t; p < 480; p += 256) { float v = g_yA[p*128+c]; s += v; q = fmaf(v,v,q); }
    rs[t] = s; rq[t] = q;
    __syncthreads();
    for (int o = 128; o > 0; o >>= 1) {
        if (t < o) { rs[t] += rs[t+o]; rq[t] += rq[t+o]; }
        __syncthreads();
    }
    if (t == 0) {
        float mean = rs[0] * (1.f/480.f);
        float var  = rq[0] * (1.f/480.f) - mean*mean;
        float scl  = g[c] * rsqrtf(var + 1e-5f);
        g_scaleA[c] = scl;
        g_biasA[c]  = b[c] - mean*scl;
    }
}

__global__ void k_gemmB(const float* __restrict__ W) { // (128,128)
    int p = blockIdx.x, c = threadIdx.x;
    __shared__ float z[128];
    z[c] = fmaxf(fmaf(g_scaleA[c], g_yA[p*128+c], g_biasA[c]), 0.f);
    __syncthreads();
    float acc = 0.f;
    const float* w = W + c*128;
    #pragma unroll
    for (int i = 0; i < 128; i++) acc = fmaf(w[i], z[i], acc);
    g_yB[p*128+c] = acc;
}

__global__ void k_statsB(const float* __restrict__ g, const float* __restrict__ b) {
    __shared__ float rs[256], rq[256];
    int c = blockIdx.x, t = threadIdx.x; // 128 blocks x 256
    float s = 0.f, q = 0.f;
    for (int p = t; p < 480; p += 256) { float v = g_yB[p*128+c]; s += v; q = fmaf(v,v,q); }
    rs[t] = s; rq[t] = q;
    __syncthreads();
    for (int o = 128; o > 0; o >>= 1) {
        if (t < o) { rs[t] += rs[t+o]; rq[t] += rq[t+o]; }
        __syncthreads();
    }
    if (t == 0) {
        float mean = rs[0] * (1.f/480.f);
        float var  = rq[0] * (1.f/480.f) - mean*mean;
        float scl  = g[c] * rsqrtf(var + 1e-5f);
        g_scaleB[c] = scl;
        g_biasB[c]  = b[c] - mean*scl;
    }
}

// s3in assembly: max-over-3 with BN monotone trick (160 blocks x 128 threads)
__global__ void k_s3in() {
    int bs = blockIdx.x, c = threadIdx.x;
    float scl = g_scaleB[c], bi = g_biasB[c];
    float v0 = g_yB[(bs*3+0)*128+c];
    float v1 = g_yB[(bs*3+1)*128+c];
    float v2 = g_yB[(bs*3+2)*128+c];
    float v  = (scl >= 0.f) ? fmaxf(v0, fmaxf(v1, v2)) : fminf(v0, fminf(v1, v2));
    g_s3in[bs*131 + 3 + c] = fmaxf(fmaf(scl, v, bi), 0.f);
}

__global__ void k_gemmC(const float* __restrict__ W) { // (256,131)
    int bs = blockIdx.x, c = threadIdx.x; // 160 x 256
    __shared__ float f[131];
    if (c < 131) f[c] = g_s3in[bs*131+c];
    __syncthreads();
    float acc = 0.f;
    const float* w = W + c*131;
    #pragma unroll
    for (int i = 0; i < 131; i++) acc = fmaf(w[i], f[i], acc);
    g_yC[bs*256+c] = acc;
}

__global__ void k_statsC(const float* __restrict__ g, const float* __restrict__ b) {
    __shared__ float rs[256], rq[256];
    int c = blockIdx.x, t = threadIdx.x; // 256 blocks x 256
    float s = 0.f, q = 0.f;
    if (t < 160) { float v = g_yC[t*256+c]; s = v; q = v*v; }
    rs[t] = s; rq[t] = q;
    __syncthreads();
    for (int o = 128; o > 0; o >>= 1) {
        if (t < o) { rs[t] += rs[t+o]; rq[t] += rq[t+o]; }
        __syncthreads();
    }
    if (t == 0) {
        float mean = rs[0] * (1.f/160.f);
        float var  = rq[0] * (1.f/160.f) - mean*mean;
        float scl  = g[c] * rsqrtf(var + 1e-5f);
        g_scaleC[c] = scl;
        g_biasC[c]  = b[c] - mean*scl;
    }
}

__global__ void k_gemmD(const float* __restrict__ W) { // (256,256)
    int bs = blockIdx.x, c = threadIdx.x;
    __shared__ float z[256];
    z[c] = fmaxf(fmaf(g_scaleC[c], g_yC[bs*256+c], g_biasC[c]), 0.f);
    __syncthreads();
    float acc = 0.f;
    const float* w = W + c*256;
    #pragma unroll
    for (int i = 0; i < 256; i++) acc = fmaf(w[i], z[i], acc);
    g_yD[bs*256+c] = acc;
}

__global__ void k_statsD(const float* __restrict__ g, const float* __restrict__ b) {
    __shared__ float rs[256], rq[256];
    int c = blockIdx.x, t = threadIdx.x; // 256 blocks x 256
    float s = 0.f, q = 0.f;
    if (t < 160) { float v = g_yD[t*256+c]; s = v; q = v*v; }
    rs[t] = s; rq[t] = q;
    __syncthreads();
    for (int o = 128; o > 0; o >>= 1) {
        if (t < o) { rs[t] += rs[t+o]; rq[t] += rq[t+o]; }
        __syncthreads();
    }
    if (t == 0) {
        float mean = rs[0] * (1.f/160.f);
        float var  = rq[0] * (1.f/160.f) - mean*mean;
        float scl  = g[c] * rsqrtf(var + 1e-5f);
        g_scaleD[c] = scl;
        g_biasD[c]  = b[c] - mean*scl;
    }
}

// final output: max over 5 splits with BN monotone trick (32 blocks x 256 threads)
__global__ void k_out(float* __restrict__ out) {
    int bb = blockIdx.x, c = threadIdx.x;
    float scl = g_scaleD[c], bi = g_biasD[c];
    float v = (scl >= 0.f) ? -3.402823e38f : 3.402823e38f;
    #pragma unroll
    for (int ss = 0; ss < 5; ss++) {
        float y = g_yD[(bb*5+ss)*256+c];
        v = (scl >= 0.f) ? fmaxf(v, y) : fminf(v, y);
    }
    out[bb*256+c] = fmaxf(fmaf(scl, v, bi), 0.f);
}

// ---------------- launch ----------------
extern "C" void kernel_launch(void* const* d_in, const int* in_sizes, int n_in,
                              void* d_out, int out_size) {
    const float* x      = (const float*)d_in[0];
    const float* la0_w0 = (const float*)d_in[1];
    const float* la0_g0 = (const float*)d_in[2];
    const float* la0_b0 = (const float*)d_in[3];
    const float* la0_w1 = (const float*)d_in[4];
    const float* la0_g1 = (const float*)d_in[5];
    const float* la0_b1 = (const float*)d_in[6];
    const float* la1_w0 = (const float*)d_in[7];
    const float* la1_g0 = (const float*)d_in[8];
    const float* la1_b0 = (const float*)d_in[9];
    const float* la1_w1 = (const float*)d_in[10];
    const float* la1_g1 = (const float*)d_in[11];
    const float* la1_b1 = (const float*)d_in[12];
    const float* la2_w0 = (const float*)d_in[13];
    const float* la2_g0 = (const float*)d_in[14];
    const float* la2_b0 = (const float*)d_in[15];
    const float* la2_w1 = (const float*)d_in[16];
    const float* la2_g1 = (const float*)d_in[17];
    const float* la2_b1 = (const float*)d_in[18];
    float* out = (float*)d_out;

    // smem: 2048 + 2048 (W hi/lo) + 2*128*ZSTR (Z hi/lo) + 2048 (red) + 256 + 8
    const int SMEM_MAIN = (2048 + 2048 + 2*TILE_P*ZSTR + 2048 + 256 + 8) * 4;
    cudaFuncSetAttribute(k_main, cudaFuncAttributeMaxDynamicSharedMemorySize, SMEM_MAIN);

    k_centroid<<<NG, 256>>>(x, out);
    k_bn0<<<1, 192>>>(la0_w0, la0_g0, la0_b0);
    k_main<<<NG, 256, SMEM_MAIN>>>(x, la0_w1);
    k_bn1_stats<<<64, 256>>>(la0_g1, la0_b1);
    k_lf1<<<120, 256>>>(out);
    k_feats2<<<1, 160>>>();
    k_gemmA<<<480, 128>>>(la1_w0);
    k_statsA<<<128, 256>>>(la1_g0, la1_b0);
    k_gemmB<<<480, 128>>>(la1_w1);
    k_statsB<<<128, 256>>>(la1_g1, la1_b1);
    k_s3in<<<160, 128>>>();
    k_gemmC<<<160, 256>>>(la2_w0);
    k_statsC<<<256, 256>>>(la2_g0, la2_b0);
    k_gemmD<<<160, 256>>>(la2_w1);
    k_statsD<<<256, 256>>>(la2_g1, la2_b1);
    k_out<<<32, 256>>>(out);
}